// round 14
// baseline (speedup 1.0000x reference)
#include <cuda_runtime.h>
#include <cuda_fp16.h>
#include <cstdint>
#include <math.h>

#define B_   8192
#define T_   10
#define F_   561
#define H_   256
#define O_   12
#define NBT  (B_ * T_)          // 81920
#define KXS  576                // 561 padded to 9*64 (single-term X)
#define AXPW 256                // xp stored as single fp16 segment
#define K4H  1024               // Act row: [h0hi|h0lo|h1hi|h1lo]
#define KW   768                // recurrent weight row: [W_in | W_hh | W_hh]
#define G4H  1024

#define SWZ128(off) ((off) ^ (((off) >> 3) & 0x70))

__device__ __forceinline__ uint32_t smem_u32(const void* p) {
    uint32_t a;
    asm("{ .reg .u64 t; cvta.to.shared.u64 t, %1; cvt.u32.u64 %0, t; }" : "=r"(a) : "l"(p));
    return a;
}
__device__ __forceinline__ void ldsm_x4(uint32_t* r, uint32_t addr) {
    asm volatile("ldmatrix.sync.aligned.m8n8.x4.shared.b16 {%0,%1,%2,%3}, [%4];"
                 : "=r"(r[0]), "=r"(r[1]), "=r"(r[2]), "=r"(r[3]) : "r"(addr));
}
__device__ __forceinline__ void mma_f16(float* d, const uint32_t* a, uint32_t b0, uint32_t b1) {
    asm volatile("mma.sync.aligned.m16n8k16.row.col.f32.f16.f16.f32 "
                 "{%0,%1,%2,%3}, {%4,%5,%6,%7}, {%8,%9}, {%0,%1,%2,%3};"
                 : "+f"(d[0]), "+f"(d[1]), "+f"(d[2]), "+f"(d[3])
                 : "r"(a[0]), "r"(a[1]), "r"(a[2]), "r"(a[3]), "r"(b0), "r"(b1));
}

// ---------- fast activations (approx; abs err ~1e-6, invisible vs fp16 rounding) ----------
#define LOG2E 1.4426950408889634f
__device__ __forceinline__ float fexp2(float x){ float r; asm("ex2.approx.f32 %0, %1;" : "=f"(r) : "f"(x)); return r; }
__device__ __forceinline__ float frcpa(float x){ float r; asm("rcp.approx.f32 %0, %1;" : "=f"(r) : "f"(x)); return r; }
__device__ __forceinline__ float fsig(float x){ return frcpa(1.f + fexp2(-LOG2E * x)); }
__device__ __forceinline__ float ftanh_(float x){
    float xc = fminf(fmaxf(x, -20.f), 20.f);
    float e = fexp2(2.f * LOG2E * xc);
    return (e - 1.f) * frcpa(e + 1.f);
}
__device__ __forceinline__ void split_f16(float x, __half& hi, __half& lo) {
    hi = __float2half_rn(x);
    lo = __float2half_rn(x - __half2float(hi));
}

// ======================= scratch =======================
__device__ __half g_Xh[(size_t)NBT * KXS];          // [NBT,576] = [Xhi(561)|pad]
__device__ __half g_Axp[(size_t)NBT * AXPW];        // [NBT,256] fp16 xp
__device__ __half g_ActA[(size_t)B_ * K4H];         // [B,1024]: [h0hi|h0lo|h1hi|h1lo]
__device__ __half g_ActB[(size_t)B_ * K4H];
__device__ float  g_c0[B_ * H_];
__device__ float  g_c1[B_ * H_];
__device__ float  g_hs[(size_t)NBT * H_];
__device__ __half g_WbInp[(size_t)H_ * KXS];        // [256,576] = [Whi|pad]
__device__ __half g_Wc0[(size_t)G4H * KW];          // paired-gate interleave [Wih0|Whh0|Whh0]
__device__ __half g_Wc1[(size_t)G4H * KW];
__device__ float  g_bias0[G4H];                     // float4 per unit: (bi,bf,bg,bo)
__device__ float  g_bias1[G4H];

// ======================= tile config =======================
#define TM_ 128
#define TN_ 128
#define KC  64
#define SM_A0  0
#define SM_A1  16384
#define SM_B0  32768
#define SM_B1  49152
#define SM_TOTAL 65536

// ======================= xp GEMM: Axp = fp16(X @ W_inp^T + b) =======================
__global__ void __launch_bounds__(256)
xp_gemm(const __half* __restrict__ A, const __half* __restrict__ Bw,
        const float* __restrict__ bias, __half* __restrict__ Aout)
{
    extern __shared__ char smem[];
    const uint32_t sb = smem_u32(smem);
    const int tid  = threadIdx.x;
    const int wid  = tid >> 5;
    const int lane = tid & 31;
    const int wm   = wid >> 1;
    const int wn   = wid & 1;
    const long rowBase = (long)blockIdx.y * TM_;
    const long colBase = (long)blockIdx.x * TN_;
    const uint32_t abuf[2] = { sb + SM_A0, sb + SM_A1 };
    const uint32_t bbuf[2] = { sb + SM_B0, sb + SM_B1 };

    float acc[2][8][4];
#pragma unroll
    for (int i = 0; i < 2; i++)
#pragma unroll
        for (int j = 0; j < 8; j++)
#pragma unroll
            for (int k = 0; k < 4; k++) acc[i][j][k] = 0.f;

    const int nch = KXS / KC;   // 9

#define LOAD_CHUNK1(c, buf) do { \
    _Pragma("unroll") \
    for (int l = 0; l < 4; l++) { \
        int idx = tid + 256 * l; int r = idx >> 3, v = idx & 7; \
        const void* gp = A + (rowBase + r) * (long)KXS + (long)(c) * KC + v * 8; \
        uint32_t s = abuf[buf] + SWZ128(r * 128 + v * 16); \
        asm volatile("cp.async.cg.shared.global [%0], [%1], 16;\n" :: "r"(s), "l"(gp)); \
    } \
    _Pragma("unroll") \
    for (int l = 0; l < 4; l++) { \
        int idx = tid + 256 * l; int r = idx >> 3, v = idx & 7; \
        const void* gp = Bw + (colBase + r) * (long)KXS + (long)(c) * KC + v * 8; \
        uint32_t s = bbuf[buf] + SWZ128(r * 128 + v * 16); \
        asm volatile("cp.async.cg.shared.global [%0], [%1], 16;\n" :: "r"(s), "l"(gp)); \
    } \
    asm volatile("cp.async.commit_group;\n"); \
} while (0)

    LOAD_CHUNK1(0, 0);
    LOAD_CHUNK1(1, 1);

    for (int c = 0; c < nch; c++) {
        const int buf = c & 1;
        if (c + 1 < nch) asm volatile("cp.async.wait_group 1;\n" ::: "memory");
        else             asm volatile("cp.async.wait_group 0;\n" ::: "memory");
        __syncthreads();
        const uint32_t As = abuf[buf], Bs = bbuf[buf];
#pragma unroll
        for (int ks = 0; ks < 4; ks++) {
            uint32_t afr[2][4];
#pragma unroll
            for (int mt = 0; mt < 2; mt++) {
                int row = wm * 32 + mt * 16 + (lane & 15);
                int kc  = ks * 16 + ((lane >> 4) << 3);
                ldsm_x4(afr[mt], As + SWZ128(row * 128 + kc * 2));
            }
            uint32_t bfr[4][4];
#pragma unroll
            for (int bt = 0; bt < 4; bt++) {
                int nr = wn * 64 + bt * 16 + (lane & 7) + ((lane >> 4) << 3);
                int kc = ks * 16 + (((lane >> 3) & 1) << 3);
                ldsm_x4(bfr[bt], Bs + SWZ128(nr * 128 + kc * 2));
            }
#pragma unroll
            for (int mt = 0; mt < 2; mt++)
#pragma unroll
                for (int nt = 0; nt < 8; nt++) {
                    const uint32_t* bp = bfr[nt >> 1];
                    if (nt & 1) mma_f16(acc[mt][nt], afr[mt], bp[2], bp[3]);
                    else        mma_f16(acc[mt][nt], afr[mt], bp[0], bp[1]);
                }
        }
        __syncthreads();
        if (c + 2 < nch) LOAD_CHUNK1(c + 2, buf);
    }

#pragma unroll
    for (int mt = 0; mt < 2; mt++)
#pragma unroll
        for (int nt = 0; nt < 8; nt++) {
            long row = rowBase + wm * 32 + mt * 16 + (lane >> 2);
            long col = colBase + wn * 64 + nt * 8 + ((lane & 3) << 1);
            float2 bv = *(const float2*)&bias[col];
#pragma unroll
            for (int h = 0; h < 2; h++) {
                long r2 = row + 8 * h;
                float vx = acc[mt][nt][2 * h + 0] + bv.x;
                float vy = acc[mt][nt][2 * h + 1] + bv.y;
                *(__half2*)&Aout[r2 * AXPW + col] =
                    __halves2half2(__float2half_rn(vx), __float2half_rn(vy));
            }
        }
}

// ======================= fused GEMM + LSTM cell (2 jobs per launch) =======================
// gates = [A1 (4 chunks) | A2 (8 chunks)] @ Wc^T + bias, paired-gate interleave:
// 16-col window w holds units w*4..w*4+3; cols 0-7 = (i,f) pairs, cols 8-15 = (g,o) pairs.
// => each thread's acc pairs (nt=2a, 2a+1) hold complete gate quads -> register-direct cell update.
#define NCH2 12

__global__ void __launch_bounds__(256)
gemm_lstm(const __half* A1a, long lda1a, const __half* A2a,
          const __half* Wca, const float* biasa, float* csta,
          __half* wacta, int woffa, float* hsa, int ta, float* hna, float* cna,
          const __half* A1b, long lda1b, const __half* A2b,
          const __half* Wcb, const float* biasb, float* cstb,
          __half* wactb, int woffb, float* hsb, int tb, float* hnb, float* cnb)
{
    const bool sec = (blockIdx.x >= 8);
    const __half* A1   = sec ? A1b : A1a;
    const long lda1    = sec ? lda1b : lda1a;
    const __half* A2   = sec ? A2b : A2a;
    const __half* Wc   = sec ? Wcb : Wca;
    const float* biasF = sec ? biasb : biasa;
    float* cst         = sec ? cstb : csta;
    __half* Wact       = sec ? wactb : wacta;
    const int actOff   = sec ? woffb : woffa;
    float* hsp         = sec ? hsb : hsa;
    const int t        = sec ? tb : ta;
    float* hnp         = sec ? hnb : hna;
    float* cnp         = sec ? cnb : cna;
    const int bx       = blockIdx.x & 7;

    extern __shared__ char smem[];
    const uint32_t sb = smem_u32(smem);
    const int tid  = threadIdx.x;
    const int wid  = tid >> 5;
    const int lane = tid & 31;
    const int wm   = wid >> 1;
    const int wn   = wid & 1;
    const long rowBase = (long)blockIdx.y * TM_;
    const long colBase = (long)bx * TN_;
    const uint32_t abuf[2] = { sb + SM_A0, sb + SM_A1 };
    const uint32_t bbuf[2] = { sb + SM_B0, sb + SM_B1 };

    float acc[2][8][4];
#pragma unroll
    for (int i = 0; i < 2; i++)
#pragma unroll
        for (int j = 0; j < 8; j++)
#pragma unroll
            for (int k = 0; k < 4; k++) acc[i][j][k] = 0.f;

#define LOAD_CHUNK2(c, buf) do { \
    const __half* Asrc; long Alda; int cl; \
    if ((c) < 4) { Asrc = A1; Alda = lda1; cl = (c); } \
    else         { Asrc = A2; Alda = K4H;  cl = (c) - 4; } \
    _Pragma("unroll") \
    for (int l = 0; l < 4; l++) { \
        int idx = tid + 256 * l; int r = idx >> 3, v = idx & 7; \
        const void* gp = Asrc + (rowBase + r) * Alda + (long)cl * KC + v * 8; \
        uint32_t s = abuf[buf] + SWZ128(r * 128 + v * 16); \
        asm volatile("cp.async.cg.shared.global [%0], [%1], 16;\n" :: "r"(s), "l"(gp)); \
    } \
    _Pragma("unroll") \
    for (int l = 0; l < 4; l++) { \
        int idx = tid + 256 * l; int r = idx >> 3, v = idx & 7; \
        const void* gp = Wc + (colBase + r) * (long)KW + (long)(c) * KC + v * 8; \
        uint32_t s = bbuf[buf] + SWZ128(r * 128 + v * 16); \
        asm volatile("cp.async.cg.shared.global [%0], [%1], 16;\n" :: "r"(s), "l"(gp)); \
    } \
    asm volatile("cp.async.commit_group;\n"); \
} while (0)

    LOAD_CHUNK2(0, 0);
    LOAD_CHUNK2(1, 1);

    for (int c = 0; c < NCH2; c++) {
        const int buf = c & 1;
        if (c + 1 < NCH2) asm volatile("cp.async.wait_group 1;\n" ::: "memory");
        else              asm volatile("cp.async.wait_group 0;\n" ::: "memory");
        __syncthreads();
        const uint32_t As = abuf[buf], Bs = bbuf[buf];
#pragma unroll
        for (int ks = 0; ks < 4; ks++) {
            uint32_t afr[2][4];
#pragma unroll
            for (int mt = 0; mt < 2; mt++) {
                int row = wm * 32 + mt * 16 + (lane & 15);
                int kc  = ks * 16 + ((lane >> 4) << 3);
                ldsm_x4(afr[mt], As + SWZ128(row * 128 + kc * 2));
            }
            uint32_t bfr[4][4];
#pragma unroll
            for (int bt = 0; bt < 4; bt++) {
                int nr = wn * 64 + bt * 16 + (lane & 7) + ((lane >> 4) << 3);
                int kc = ks * 16 + (((lane >> 3) & 1) << 3);
                ldsm_x4(bfr[bt], Bs + SWZ128(nr * 128 + kc * 2));
            }
#pragma unroll
            for (int mt = 0; mt < 2; mt++)
#pragma unroll
                for (int nt = 0; nt < 8; nt++) {
                    const uint32_t* bp = bfr[nt >> 1];
                    if (nt & 1) mma_f16(acc[mt][nt], afr[mt], bp[2], bp[3]);
                    else        mma_f16(acc[mt][nt], afr[mt], bp[0], bp[1]);
                }
        }
        __syncthreads();
        if (c + 2 < NCH2) LOAD_CHUNK2(c + 2, buf);
    }

    // ---------- register-direct fused LSTM epilogue (no smem, no syncs) ----------
    const int ul = lane & 3;
    const int rsub = lane >> 2;
#pragma unroll
    for (int mt = 0; mt < 2; mt++) {
#pragma unroll
        for (int a = 0; a < 4; a++) {
            const int u = bx * 32 + wn * 16 + a * 4 + ul;     // global unit 0..255
            const float4 bv = *(const float4*)&biasF[u * 4];
#pragma unroll
            for (int hh = 0; hh < 2; hh++) {
                long b = rowBase + wm * 32 + mt * 16 + rsub + 8 * hh;
                float gi = acc[mt][2 * a][2 * hh + 0] + bv.x;
                float gf = acc[mt][2 * a][2 * hh + 1] + bv.y;
                float gg = acc[mt][2 * a + 1][2 * hh + 0] + bv.z;
                float go = acc[mt][2 * a + 1][2 * hh + 1] + bv.w;
                long cidx = b * H_ + u;
                float c_new = fsig(gf) * cst[cidx] + fsig(gi) * ftanh_(gg);
                float h_new = fsig(go) * ftanh_(c_new);
                cst[cidx] = c_new;
                __half hi, lo; split_f16(h_new, hi, lo);
                __half* ap = Wact + b * K4H + actOff;
                ap[u] = hi; ap[u + 256] = lo;
                if (hsp) hsp[(b * T_ + t) * H_ + u] = h_new;
                if (hnp) { hnp[cidx] = h_new; cnp[cidx] = c_new; }
            }
        }
    }
}

// ======================= prep kernels =======================
__global__ void zero_misc_kernel() {
    long n = (long)B_ * K4H;
    for (long i = blockIdx.x * (long)blockDim.x + threadIdx.x; i < n; i += (long)gridDim.x * blockDim.x) {
        g_ActA[i] = __float2half(0.f);
        g_ActB[i] = __float2half(0.f);
    }
    for (int i = blockIdx.x * blockDim.x + threadIdx.x; i < B_ * H_; i += gridDim.x * blockDim.x) {
        g_c0[i] = 0.f; g_c1[i] = 0.f;
    }
    for (int i = blockIdx.x * blockDim.x + threadIdx.x; i < H_ * (KXS - F_); i += gridDim.x * blockDim.x) {
        int r = i / (KXS - F_), c = i % (KXS - F_);
        g_WbInp[(size_t)r * KXS + F_ + c] = __float2half(0.f);
    }
}

__global__ void split_X_kernel(const float* __restrict__ X) {
    long n = (long)NBT * KXS;
    for (long i = blockIdx.x * (long)blockDim.x + threadIdx.x; i < n; i += (long)gridDim.x * blockDim.x) {
        long row = i / KXS; int col = (int)(i % KXS);
        g_Xh[i] = (col < F_) ? __float2half_rn(X[row * F_ + col]) : __float2half(0.f);
    }
}

__global__ void split_Winp_kernel(const float* __restrict__ W) {
    int n = H_ * F_;
    for (int i = blockIdx.x * blockDim.x + threadIdx.x; i < n; i += gridDim.x * blockDim.x) {
        int r = i / F_, k = i % F_;
        g_WbInp[(size_t)r * KXS + k] = __float2half_rn(W[i]);
    }
}

// Paired-gate interleave: dst col n -> (unit j, gate g):
//   window = n>>4, pos = n&15, half8 = pos>>3, jl = (pos&7)>>1, e = pos&1
//   j = window*4 + jl, g = half8*2 + e, src row r = g*256 + j.
// Row layout (768): [W_in | W_hh | W_hh]. Bias stored as float4 per unit: biasF[j*4+g].
__global__ void fuse_W_kernel(const float* __restrict__ Wih, const float* __restrict__ Whh,
                              const float* __restrict__ bih, const float* __restrict__ bhh,
                              __half* __restrict__ Wc, float* __restrict__ biasF)
{
    int total = G4H * H_;
    for (int i = blockIdx.x * blockDim.x + threadIdx.x; i < total; i += gridDim.x * blockDim.x) {
        int n = i >> 8, k = i & 255;
        int window = n >> 4, pos = n & 15;
        int half8 = pos >> 3, jl = (pos & 7) >> 1, e = pos & 1;
        int j = window * 4 + jl;
        int g = half8 * 2 + e;
        int r = g * 256 + j;
        __half* row = Wc + (size_t)n * KW;
        __half wi = __float2half_rn(Wih[r * 256 + k]);
        __half wh = __float2half_rn(Whh[r * 256 + k]);
        row[k] = wi;
        row[256 + k] = wh;
        row[512 + k] = wh;
        if (k == 0) biasF[j * 4 + g] = bih[r] + bhh[r];
    }
}

__global__ void __launch_bounds__(256)
proj_kernel(const float* __restrict__ W_out, const float* __restrict__ b_out, float* __restrict__ out)
{
    __shared__ float Ws[O_ * H_];
    __shared__ float bs[O_];
    for (int i = threadIdx.x; i < O_ * H_; i += blockDim.x) Ws[i] = W_out[i];
    if (threadIdx.x < O_) bs[threadIdx.x] = b_out[threadIdx.x];
    __syncthreads();
    int warp = threadIdx.x / 32, lane = threadIdx.x % 32;
    long row = (long)blockIdx.x * 8 + warp;
    if (row >= NBT) return;
    float x[H_ / 32];
#pragma unroll
    for (int j = 0; j < H_ / 32; j++) x[j] = g_hs[row * H_ + lane + 32 * j];
#pragma unroll
    for (int o = 0; o < O_; o++) {
        float s = 0.f;
#pragma unroll
        for (int j = 0; j < H_ / 32; j++) s = fmaf(x[j], Ws[o * H_ + lane + 32 * j], s);
#pragma unroll
        for (int off = 16; off > 0; off >>= 1) s += __shfl_xor_sync(0xffffffffu, s, off);
        if (lane == 0) out[row * O_ + o] = s + bs[o];
    }
}

// ======================= launch =======================
extern "C" void kernel_launch(void* const* d_in, const int* in_sizes, int n_in,
                              void* d_out, int out_size)
{
    (void)in_sizes; (void)n_in; (void)out_size;
    const float* X     = (const float*)d_in[0];
    const float* W_inp = (const float*)d_in[1];
    const float* b_inp = (const float*)d_in[2];
    const float* Wih0  = (const float*)d_in[3];
    const float* Whh0  = (const float*)d_in[4];
    const float* bih0  = (const float*)d_in[5];
    const float* bhh0  = (const float*)d_in[6];
    const float* Wih1  = (const float*)d_in[7];
    const float* Whh1  = (const float*)d_in[8];
    const float* bih1  = (const float*)d_in[9];
    const float* bhh1  = (const float*)d_in[10];
    const float* W_out = (const float*)d_in[11];
    const float* b_out = (const float*)d_in[12];

    float* out     = (float*)d_out;
    float* hn_base = out + (size_t)B_ * T_ * O_;
    float* cn_base = hn_base + (size_t)2 * B_ * H_;

    static bool init = false;
    static __half *Xh, *Axp, *ActA, *ActB, *WbInp, *Wc0, *Wc1;
    static float *c0, *c1, *hs, *bias0, *bias1;
    if (!init) {
        cudaGetSymbolAddress((void**)&Xh,     g_Xh);
        cudaGetSymbolAddress((void**)&Axp,    g_Axp);
        cudaGetSymbolAddress((void**)&ActA,   g_ActA);
        cudaGetSymbolAddress((void**)&ActB,   g_ActB);
        cudaGetSymbolAddress((void**)&WbInp,  g_WbInp);
        cudaGetSymbolAddress((void**)&Wc0,    g_Wc0);
        cudaGetSymbolAddress((void**)&Wc1,    g_Wc1);
        cudaGetSymbolAddress((void**)&c0,     g_c0);
        cudaGetSymbolAddress((void**)&c1,     g_c1);
        cudaGetSymbolAddress((void**)&hs,     g_hs);
        cudaGetSymbolAddress((void**)&bias0,  g_bias0);
        cudaGetSymbolAddress((void**)&bias1,  g_bias1);
        cudaFuncSetAttribute(xp_gemm,   cudaFuncAttributeMaxDynamicSharedMemorySize, SM_TOTAL);
        cudaFuncSetAttribute(gemm_lstm, cudaFuncAttributeMaxDynamicSharedMemorySize, SM_TOTAL);
        init = true;
    }

    // prep
    zero_misc_kernel<<<1024, 256>>>();
    split_X_kernel<<<2048, 256>>>(X);
    split_Winp_kernel<<<256, 256>>>(W_inp);
    fuse_W_kernel<<<512, 256>>>(Wih0, Whh0, bih0, bhh0, Wc0, bias0);
    fuse_W_kernel<<<512, 256>>>(Wih1, Whh1, bih1, bhh1, Wc1, bias1);

    // xp = fp16(X @ W_inp^T + b_inp)
    {
        dim3 grid(H_ / TN_, NBT / TM_);   // (2, 640)
        xp_gemm<<<grid, 256, SM_TOTAL>>>(Xh, WbInp, b_inp, Axp);
    }

    // Recurrence, pipelined across the step boundary
    {
        dim3 g1(8, 64);
        const long ldxp = (long)T_ * AXPW;   // 2560

        // P: layer0(0): [xp(0) | h0(-1)=0]
        gemm_lstm<<<g1, 256, SM_TOTAL>>>(
            Axp, ldxp, ActA,
            Wc0, bias0, c0, ActB, 0,
            nullptr, 0, nullptr, nullptr,
            Axp, ldxp, ActA, Wc0, bias0, c0, ActB, 0,
            nullptr, 0, nullptr, nullptr);

        for (int i = 1; i <= 9; i++) {
            __half* bufR = ((i - 1) % 2 == 0) ? ActB : ActA;
            __half* bufW = ((i - 1) % 2 == 0) ? ActA : ActB;
            int t1 = i - 1;
            int t0 = i;
            bool l0last = (t0 == T_ - 1);
            dim3 g2(16, 64);
            gemm_lstm<<<g2, 256, SM_TOTAL>>>(
                // job0: layer1(t1) = [h0(t1)hi | h1(t1-1) hi,lo]
                bufR, (long)K4H, bufR + 512,
                Wc1, bias1, c1, bufW, 512,
                hs, t1, nullptr, nullptr,
                // job1: layer0(t0) = [xp(t0) | h0(t0-1) hi,lo]
                Axp + (size_t)t0 * AXPW, ldxp, bufR,
                Wc0, bias0, c0, bufW, 0,
                nullptr, t0,
                l0last ? hn_base : nullptr, l0last ? cn_base : nullptr);
        }

        // F: layer1(9); bufW_9 = ActA
        gemm_lstm<<<g1, 256, SM_TOTAL>>>(
            ActA, (long)K4H, ActA + 512,
            Wc1, bias1, c1, ActB, 512,
            hs, T_ - 1, hn_base + (size_t)B_ * H_, cn_base + (size_t)B_ * H_,
            ActA, (long)K4H, ActA + 512, Wc1, bias1, c1, ActB, 512,
            hs, T_ - 1, nullptr, nullptr);
    }

    // outputs = hs @ W_out^T + b_out
    proj_kernel<<<NBT / 8, 256>>>(W_out, b_out, out);
}

// round 16
// speedup vs baseline: 1.6744x; 1.6744x over previous
#include <cuda_runtime.h>
#include <cuda_fp16.h>
#include <cstdint>
#include <math.h>

#define B_   8192
#define T_   10
#define F_   561
#define H_   256
#define O_   12
#define NBT  (B_ * T_)          // 81920
#define KXS  576                // 561 padded to 9*64
#define AXPW 256                // xp stored as single fp16 segment
#define K4H  1024               // Act row: [h0hi|h0lo|h1hi|h1lo]
#define KW   768                // recurrent weight row: [W_in | W_hh | W_hh]
#define G4H  1024
#define NJOBS 20                // 2 per step
#define ROWBLKS 64

#define SWZ128(off) ((off) ^ (((off) >> 3) & 0x70))

__device__ __forceinline__ uint32_t smem_u32(const void* p) {
    uint32_t a;
    asm("{ .reg .u64 t; cvta.to.shared.u64 t, %1; cvt.u32.u64 %0, t; }" : "=r"(a) : "l"(p));
    return a;
}
__device__ __forceinline__ void ldsm_x4(uint32_t* r, uint32_t addr) {
    asm volatile("ldmatrix.sync.aligned.m8n8.x4.shared.b16 {%0,%1,%2,%3}, [%4];"
                 : "=r"(r[0]), "=r"(r[1]), "=r"(r[2]), "=r"(r[3]) : "r"(addr));
}
__device__ __forceinline__ void mma_f16(float* d, const uint32_t* a, uint32_t b0, uint32_t b1) {
    asm volatile("mma.sync.aligned.m16n8k16.row.col.f32.f16.f16.f32 "
                 "{%0,%1,%2,%3}, {%4,%5,%6,%7}, {%8,%9}, {%0,%1,%2,%3};"
                 : "+f"(d[0]), "+f"(d[1]), "+f"(d[2]), "+f"(d[3])
                 : "r"(a[0]), "r"(a[1]), "r"(a[2]), "r"(a[3]), "r"(b0), "r"(b1));
}

// ---------- fast activations ----------
#define LOG2E 1.4426950408889634f
__device__ __forceinline__ float fexp2(float x){ float r; asm("ex2.approx.f32 %0, %1;" : "=f"(r) : "f"(x)); return r; }
__device__ __forceinline__ float frcpa(float x){ float r; asm("rcp.approx.f32 %0, %1;" : "=f"(r) : "f"(x)); return r; }
__device__ __forceinline__ float fsig(float x){ return frcpa(1.f + fexp2(-LOG2E * x)); }
__device__ __forceinline__ float ftanh_(float x){
    float xc = fminf(fmaxf(x, -20.f), 20.f);
    float e = fexp2(2.f * LOG2E * xc);
    return (e - 1.f) * frcpa(e + 1.f);
}
__device__ __forceinline__ void split_f16(float x, __half& hi, __half& lo) {
    hi = __float2half_rn(x);
    lo = __float2half_rn(x - __half2float(hi));
}

// ======================= scratch =======================
__device__ __half g_Xh[(size_t)NBT * KXS];
__device__ __half g_Axp[(size_t)NBT * AXPW];
__device__ __half g_Act[(size_t)(T_ + 1) * B_ * K4H];   // per-step h buffers; Act[0] = zeros
__device__ float  g_c0[B_ * H_];
__device__ float  g_c1[B_ * H_];
__device__ float  g_hs[(size_t)NBT * H_];
__device__ __half g_WbInp[(size_t)H_ * KXS];
__device__ __half g_Wc0[(size_t)G4H * KW];              // gate-interleave n=j*4+g, [W_in|W_hh|W_hh]
__device__ __half g_Wc1[(size_t)G4H * KW];
__device__ float  g_bias0[G4H];
__device__ float  g_bias1[G4H];
__device__ int    g_flags[NJOBS * ROWBLKS];

// ======================= tile config =======================
#define TM_ 128
#define TN_ 128
#define KC  64
#define SM_A0  0
#define SM_A1  16384
#define SM_B0  32768
#define SM_B1  49152
#define SM_TOTAL 65536
#define STAGE_LD 72

// ======================= xp GEMM: Axp = fp16(X @ W_inp^T + b) =======================
__global__ void __launch_bounds__(256)
xp_gemm(const __half* __restrict__ A, const __half* __restrict__ Bw,
        const float* __restrict__ bias, __half* __restrict__ Aout)
{
    extern __shared__ char smem[];
    const uint32_t sb = smem_u32(smem);
    const int tid  = threadIdx.x;
    const int wid  = tid >> 5;
    const int lane = tid & 31;
    const int wm   = wid >> 1;
    const int wn   = wid & 1;
    const long rowBase = (long)blockIdx.y * TM_;
    const long colBase = (long)blockIdx.x * TN_;
    const uint32_t abuf[2] = { sb + SM_A0, sb + SM_A1 };
    const uint32_t bbuf[2] = { sb + SM_B0, sb + SM_B1 };

    float acc[2][8][4];
#pragma unroll
    for (int i = 0; i < 2; i++)
#pragma unroll
        for (int j = 0; j < 8; j++)
#pragma unroll
            for (int k = 0; k < 4; k++) acc[i][j][k] = 0.f;

    const int nch = KXS / KC;   // 9

#define LOAD_CHUNK1(c, buf) do { \
    _Pragma("unroll") \
    for (int l = 0; l < 4; l++) { \
        int idx = tid + 256 * l; int r = idx >> 3, v = idx & 7; \
        const void* gp = A + (rowBase + r) * (long)KXS + (long)(c) * KC + v * 8; \
        uint32_t s = abuf[buf] + SWZ128(r * 128 + v * 16); \
        asm volatile("cp.async.cg.shared.global [%0], [%1], 16;\n" :: "r"(s), "l"(gp)); \
    } \
    _Pragma("unroll") \
    for (int l = 0; l < 4; l++) { \
        int idx = tid + 256 * l; int r = idx >> 3, v = idx & 7; \
        const void* gp = Bw + (colBase + r) * (long)KXS + (long)(c) * KC + v * 8; \
        uint32_t s = bbuf[buf] + SWZ128(r * 128 + v * 16); \
        asm volatile("cp.async.cg.shared.global [%0], [%1], 16;\n" :: "r"(s), "l"(gp)); \
    } \
    asm volatile("cp.async.commit_group;\n"); \
} while (0)

    LOAD_CHUNK1(0, 0);
    LOAD_CHUNK1(1, 1);

    for (int c = 0; c < nch; c++) {
        const int buf = c & 1;
        if (c + 1 < nch) asm volatile("cp.async.wait_group 1;\n" ::: "memory");
        else             asm volatile("cp.async.wait_group 0;\n" ::: "memory");
        __syncthreads();
        const uint32_t As = abuf[buf], Bs = bbuf[buf];
#pragma unroll
        for (int ks = 0; ks < 4; ks++) {
            uint32_t afr[2][4];
#pragma unroll
            for (int mt = 0; mt < 2; mt++) {
                int row = wm * 32 + mt * 16 + (lane & 15);
                int kc  = ks * 16 + ((lane >> 4) << 3);
                ldsm_x4(afr[mt], As + SWZ128(row * 128 + kc * 2));
            }
            uint32_t bfr[4][4];
#pragma unroll
            for (int bt = 0; bt < 4; bt++) {
                int nr = wn * 64 + bt * 16 + (lane & 7) + ((lane >> 4) << 3);
                int kc = ks * 16 + (((lane >> 3) & 1) << 3);
                ldsm_x4(bfr[bt], Bs + SWZ128(nr * 128 + kc * 2));
            }
#pragma unroll
            for (int mt = 0; mt < 2; mt++)
#pragma unroll
                for (int nt = 0; nt < 8; nt++) {
                    const uint32_t* bp = bfr[nt >> 1];
                    if (nt & 1) mma_f16(acc[mt][nt], afr[mt], bp[2], bp[3]);
                    else        mma_f16(acc[mt][nt], afr[mt], bp[0], bp[1]);
                }
        }
        __syncthreads();
        if (c + 2 < nch) LOAD_CHUNK1(c + 2, buf);
    }

#pragma unroll
    for (int mt = 0; mt < 2; mt++)
#pragma unroll
        for (int nt = 0; nt < 8; nt++) {
            long row = rowBase + wm * 32 + mt * 16 + (lane >> 2);
            long col = colBase + wn * 64 + nt * 8 + ((lane & 3) << 1);
            float2 bv = *(const float2*)&bias[col];
#pragma unroll
            for (int h = 0; h < 2; h++) {
                long r2 = row + 8 * h;
                float vx = acc[mt][nt][2 * h + 0] + bv.x;
                float vy = acc[mt][nt][2 * h + 1] + bv.y;
                *(__half2*)&Aout[r2 * AXPW + col] =
                    __halves2half2(__float2half_rn(vx), __float2half_rn(vy));
            }
        }
}

// ======================= persistent fused recurrence =======================
// One launch: 20 jobs x 512 tiles. job = 2t (layer0(t)) or 2t+1 (layer1(t)).
// layer0(t): gates = [xp(t) | h0(t-1) hi,lo] @ Wc0^T; writes Act[t+1] off 0 (hi) / 256 (lo)
// layer1(t): gates = [h0(t) hi | h1(t-1) hi,lo] @ Wc1^T; writes Act[t+1] off 512/768
// Dependency via g_flags[job*64+rowblk] (8 colblock producers per row-block).
#define NCH2 12

__global__ void __launch_bounds__(256)
lstm_persist(const __half* __restrict__ Axp, float* __restrict__ hs,
             float* __restrict__ hn_base, float* __restrict__ cn_base)
{
    const int job    = blockIdx.x >> 9;
    const int within = blockIdx.x & 511;
    const int rowblk = within >> 3;
    const int bx     = within & 7;
    const int t      = job >> 1;
    const int lay    = job & 1;

    __half* ActT  = g_Act + (size_t)t * B_ * K4H;        // step t-1 results
    __half* ActT1 = g_Act + (size_t)(t + 1) * B_ * K4H;  // step t results

    const __half* A1; long lda1;
    const __half* A2;
    const __half* Wc;
    const float* biasF;
    float* cst;
    __half* Wact; int actOff;
    float* hsp; float* hnp; float* cnp;
    int depA, depB;

    if (lay == 0) {
        A1 = Axp + (size_t)t * AXPW; lda1 = (long)T_ * AXPW;
        A2 = ActT;                                   // h0(t-1) hi,lo
        Wc = g_Wc0; biasF = g_bias0; cst = g_c0;
        Wact = ActT1; actOff = 0;
        hsp = nullptr;
        hnp = (t == T_ - 1) ? hn_base : nullptr;
        cnp = (t == T_ - 1) ? cn_base : nullptr;
        depA = (t > 0) ? (job - 2) : -1;             // layer0(t-1)
        depB = -1;
    } else {
        A1 = ActT1; lda1 = (long)K4H;                // h0(t) hi (cols 0..255)
        A2 = ActT + 512;                             // h1(t-1) hi,lo
        Wc = g_Wc1; biasF = g_bias1; cst = g_c1;
        Wact = ActT1; actOff = 512;
        hsp = hs;
        hnp = (t == T_ - 1) ? (hn_base + (size_t)B_ * H_) : nullptr;
        cnp = (t == T_ - 1) ? (cn_base + (size_t)B_ * H_) : nullptr;
        depA = job - 1;                              // layer0(t)
        depB = (t > 0) ? (job - 3) : -1;             // layer1(t-1)
    }

    extern __shared__ char smem[];
    const uint32_t sb = smem_u32(smem);
    const int tid  = threadIdx.x;
    const int wid  = tid >> 5;
    const int lane = tid & 31;
    const int wm   = wid >> 1;
    const int wn   = wid & 1;
    const long rowBase = (long)rowblk * TM_;
    const long colBase = (long)bx * TN_;
    const uint32_t abuf[2] = { sb + SM_A0, sb + SM_A1 };
    const uint32_t bbuf[2] = { sb + SM_B0, sb + SM_B1 };

    // ---- wait for producers of this row-block ----
    if (tid == 0) {
        volatile int* fl = (volatile int*)g_flags;
        if (depA >= 0) while (fl[depA * ROWBLKS + rowblk] < 8) __nanosleep(64);
        if (depB >= 0) while (fl[depB * ROWBLKS + rowblk] < 8) __nanosleep(64);
        __threadfence();
    }
    __syncthreads();

    float acc[2][8][4];
#pragma unroll
    for (int i = 0; i < 2; i++)
#pragma unroll
        for (int j = 0; j < 8; j++)
#pragma unroll
            for (int k = 0; k < 4; k++) acc[i][j][k] = 0.f;

#define LOAD_CHUNK2(c, buf) do { \
    const __half* Asrc; long Alda; int cl; \
    if ((c) < 4) { Asrc = A1; Alda = lda1; cl = (c); } \
    else         { Asrc = A2; Alda = K4H;  cl = (c) - 4; } \
    _Pragma("unroll") \
    for (int l = 0; l < 4; l++) { \
        int idx = tid + 256 * l; int r = idx >> 3, v = idx & 7; \
        const void* gp = Asrc + (rowBase + r) * Alda + (long)cl * KC + v * 8; \
        uint32_t s = abuf[buf] + SWZ128(r * 128 + v * 16); \
        asm volatile("cp.async.cg.shared.global [%0], [%1], 16;\n" :: "r"(s), "l"(gp)); \
    } \
    _Pragma("unroll") \
    for (int l = 0; l < 4; l++) { \
        int idx = tid + 256 * l; int r = idx >> 3, v = idx & 7; \
        const void* gp = Wc + (colBase + r) * (long)KW + (long)(c) * KC + v * 8; \
        uint32_t s = bbuf[buf] + SWZ128(r * 128 + v * 16); \
        asm volatile("cp.async.cg.shared.global [%0], [%1], 16;\n" :: "r"(s), "l"(gp)); \
    } \
    asm volatile("cp.async.commit_group;\n"); \
} while (0)

    LOAD_CHUNK2(0, 0);
    LOAD_CHUNK2(1, 1);

    for (int c = 0; c < NCH2; c++) {
        const int buf = c & 1;
        if (c + 1 < NCH2) asm volatile("cp.async.wait_group 1;\n" ::: "memory");
        else              asm volatile("cp.async.wait_group 0;\n" ::: "memory");
        __syncthreads();
        const uint32_t As = abuf[buf], Bs = bbuf[buf];
#pragma unroll
        for (int ks = 0; ks < 4; ks++) {
            uint32_t afr[2][4];
#pragma unroll
            for (int mt = 0; mt < 2; mt++) {
                int row = wm * 32 + mt * 16 + (lane & 15);
                int kc  = ks * 16 + ((lane >> 4) << 3);
                ldsm_x4(afr[mt], As + SWZ128(row * 128 + kc * 2));
            }
            uint32_t bfr[4][4];
#pragma unroll
            for (int bt = 0; bt < 4; bt++) {
                int nr = wn * 64 + bt * 16 + (lane & 7) + ((lane >> 4) << 3);
                int kc = ks * 16 + (((lane >> 3) & 1) << 3);
                ldsm_x4(bfr[bt], Bs + SWZ128(nr * 128 + kc * 2));
            }
#pragma unroll
            for (int mt = 0; mt < 2; mt++)
#pragma unroll
                for (int nt = 0; nt < 8; nt++) {
                    const uint32_t* bp = bfr[nt >> 1];
                    if (nt & 1) mma_f16(acc[mt][nt], afr[mt], bp[2], bp[3]);
                    else        mma_f16(acc[mt][nt], afr[mt], bp[0], bp[1]);
                }
        }
        __syncthreads();
        if (c + 2 < NCH2) LOAD_CHUNK2(c + 2, buf);
    }

    // ---------- staged fused LSTM epilogue (coalesced) ----------
    __syncthreads();
    float* stage = (float*)smem;   // 128 x STAGE_LD floats
#pragma unroll 1
    for (int half = 0; half < 2; half++) {
        if (wn == half) {
#pragma unroll
            for (int mt = 0; mt < 2; mt++)
#pragma unroll
                for (int nt = 0; nt < 8; nt++) {
                    int row_l = wm * 32 + mt * 16 + (lane >> 2);
                    int col_l = nt * 8 + ((lane & 3) << 1);
                    *(float2*)&stage[row_l * STAGE_LD + col_l] =
                        make_float2(acc[mt][nt][0], acc[mt][nt][1]);
                    *(float2*)&stage[(row_l + 8) * STAGE_LD + col_l] =
                        make_float2(acc[mt][nt][2], acc[mt][nt][3]);
                }
        }
        __syncthreads();

        const int u_l = tid & 15;
        const long u_g = (long)bx * 32 + half * 16 + u_l;   // global unit 0..255
        const float4 bv = *(const float4*)&biasF[u_g * 4];
#pragma unroll
        for (int rr = 0; rr < 8; rr++) {
            int row_l = (tid >> 4) + rr * 16;
            long b = rowBase + row_l;
            float4 gv = *(float4*)&stage[row_l * STAGE_LD + u_l * 4];
            float gi = gv.x + bv.x;
            float gf = gv.y + bv.y;
            float gg = gv.z + bv.z;
            float go = gv.w + bv.w;
            long cidx = b * H_ + u_g;
            float c_new = fsig(gf) * cst[cidx] + fsig(gi) * ftanh_(gg);
            float h_new = fsig(go) * ftanh_(c_new);
            cst[cidx] = c_new;
            __half hi, lo; split_f16(h_new, hi, lo);
            __half* a = Wact + b * K4H + actOff;
            a[u_g] = hi; a[u_g + 256] = lo;
            if (hsp) hsp[(b * T_ + t) * H_ + u_g] = h_new;
            if (hnp) { hnp[cidx] = h_new; cnp[cidx] = c_new; }
        }
        __syncthreads();
    }

    // ---- publish ----
    __threadfence();
    __syncthreads();
    if (tid == 0) atomicAdd(&g_flags[job * ROWBLKS + rowblk], 1);
}

// ======================= prep kernels =======================
__global__ void zero_misc_kernel() {
    long n = (long)B_ * K4H;   // Act[0] only
    for (long i = blockIdx.x * (long)blockDim.x + threadIdx.x; i < n; i += (long)gridDim.x * blockDim.x)
        g_Act[i] = __float2half(0.f);
    for (int i = blockIdx.x * blockDim.x + threadIdx.x; i < B_ * H_; i += gridDim.x * blockDim.x) {
        g_c0[i] = 0.f; g_c1[i] = 0.f;
    }
    for (int i = blockIdx.x * blockDim.x + threadIdx.x; i < H_ * (KXS - F_); i += gridDim.x * blockDim.x) {
        int r = i / (KXS - F_), c = i % (KXS - F_);
        g_WbInp[(size_t)r * KXS + F_ + c] = __float2half(0.f);
    }
    for (int i = blockIdx.x * blockDim.x + threadIdx.x; i < NJOBS * ROWBLKS; i += gridDim.x * blockDim.x)
        g_flags[i] = 0;
}

__global__ void split_X_kernel(const float* __restrict__ X) {
    long n = (long)NBT * KXS;
    for (long i = blockIdx.x * (long)blockDim.x + threadIdx.x; i < n; i += (long)gridDim.x * blockDim.x) {
        long row = i / KXS; int col = (int)(i % KXS);
        g_Xh[i] = (col < F_) ? __float2half_rn(X[row * F_ + col]) : __float2half(0.f);
    }
}

__global__ void split_Winp_kernel(const float* __restrict__ W) {
    int n = H_ * F_;
    for (int i = blockIdx.x * blockDim.x + threadIdx.x; i < n; i += gridDim.x * blockDim.x) {
        int r = i / F_, k = i % F_;
        g_WbInp[(size_t)r * KXS + k] = __float2half_rn(W[i]);
    }
}

// Gate interleave n = j*4+g (unit-major quads); row layout [W_in | W_hh | W_hh]; fused bias.
__global__ void fuse_W_kernel(const float* __restrict__ Wih, const float* __restrict__ Whh,
                              const float* __restrict__ bih, const float* __restrict__ bhh,
                              __half* __restrict__ Wc, float* __restrict__ biasF)
{
    int total = G4H * H_;
    for (int i = blockIdx.x * blockDim.x + threadIdx.x; i < total; i += gridDim.x * blockDim.x) {
        int n = i >> 8, k = i & 255;
        int j = n >> 2, g = n & 3;
        int r = g * 256 + j;
        __half* row = Wc + (size_t)n * KW;
        __half wi = __float2half_rn(Wih[r * 256 + k]);
        __half wh = __float2half_rn(Whh[r * 256 + k]);
        row[k] = wi;
        row[256 + k] = wh;
        row[512 + k] = wh;
        if (k == 0) biasF[n] = bih[r] + bhh[r];
    }
}

__global__ void __launch_bounds__(256)
proj_kernel(const float* __restrict__ W_out, const float* __restrict__ b_out, float* __restrict__ out)
{
    __shared__ float Ws[O_ * H_];
    __shared__ float bs[O_];
    for (int i = threadIdx.x; i < O_ * H_; i += blockDim.x) Ws[i] = W_out[i];
    if (threadIdx.x < O_) bs[threadIdx.x] = b_out[threadIdx.x];
    __syncthreads();
    int warp = threadIdx.x / 32, lane = threadIdx.x % 32;
    long row = (long)blockIdx.x * 8 + warp;
    if (row >= NBT) return;
    float x[H_ / 32];
#pragma unroll
    for (int j = 0; j < H_ / 32; j++) x[j] = g_hs[row * H_ + lane + 32 * j];
#pragma unroll
    for (int o = 0; o < O_; o++) {
        float s = 0.f;
#pragma unroll
        for (int j = 0; j < H_ / 32; j++) s = fmaf(x[j], Ws[o * H_ + lane + 32 * j], s);
#pragma unroll
        for (int off = 16; off > 0; off >>= 1) s += __shfl_xor_sync(0xffffffffu, s, off);
        if (lane == 0) out[row * O_ + o] = s + bs[o];
    }
}

// ======================= launch =======================
extern "C" void kernel_launch(void* const* d_in, const int* in_sizes, int n_in,
                              void* d_out, int out_size)
{
    (void)in_sizes; (void)n_in; (void)out_size;
    const float* X     = (const float*)d_in[0];
    const float* W_inp = (const float*)d_in[1];
    const float* b_inp = (const float*)d_in[2];
    const float* Wih0  = (const float*)d_in[3];
    const float* Whh0  = (const float*)d_in[4];
    const float* bih0  = (const float*)d_in[5];
    const float* bhh0  = (const float*)d_in[6];
    const float* Wih1  = (const float*)d_in[7];
    const float* Whh1  = (const float*)d_in[8];
    const float* bih1  = (const float*)d_in[9];
    const float* bhh1  = (const float*)d_in[10];
    const float* W_out = (const float*)d_in[11];
    const float* b_out = (const float*)d_in[12];

    float* out     = (float*)d_out;
    float* hn_base = out + (size_t)B_ * T_ * O_;
    float* cn_base = hn_base + (size_t)2 * B_ * H_;

    static bool init = false;
    static __half *Xh, *Axp, *WbInp, *Wc0, *Wc1;
    static float *hs, *bias0, *bias1;
    if (!init) {
        cudaGetSymbolAddress((void**)&Xh,     g_Xh);
        cudaGetSymbolAddress((void**)&Axp,    g_Axp);
        cudaGetSymbolAddress((void**)&WbInp,  g_WbInp);
        cudaGetSymbolAddress((void**)&Wc0,    g_Wc0);
        cudaGetSymbolAddress((void**)&Wc1,    g_Wc1);
        cudaGetSymbolAddress((void**)&hs,     g_hs);
        cudaGetSymbolAddress((void**)&bias0,  g_bias0);
        cudaGetSymbolAddress((void**)&bias1,  g_bias1);
        cudaFuncSetAttribute(xp_gemm,      cudaFuncAttributeMaxDynamicSharedMemorySize, SM_TOTAL);
        cudaFuncSetAttribute(lstm_persist, cudaFuncAttributeMaxDynamicSharedMemorySize, SM_TOTAL);
        init = true;
    }

    // prep
    zero_misc_kernel<<<1024, 256>>>();
    split_X_kernel<<<2048, 256>>>(X);
    split_Winp_kernel<<<256, 256>>>(W_inp);
    fuse_W_kernel<<<512, 256>>>(Wih0, Whh0, bih0, bhh0, Wc0, bias0);
    fuse_W_kernel<<<512, 256>>>(Wih1, Whh1, bih1, bhh1, Wc1, bias1);

    // xp = fp16(X @ W_inp^T + b_inp)
    {
        dim3 grid(H_ / TN_, NBT / TM_);   // (2, 640)
        xp_gemm<<<grid, 256, SM_TOTAL>>>(Xh, WbInp, b_inp, Axp);
    }

    // full recurrence: one pipelined launch (20 jobs x 512 tiles, flag-synced)
    lstm_persist<<<NJOBS * 512, 256, SM_TOTAL>>>(Axp, hs, hn_base, cn_base);

    // outputs = hs @ W_out^T + b_out
    proj_kernel<<<NBT / 8, 256>>>(W_out, b_out, out);
}